// round 4
// baseline (speedup 1.0000x reference)
#include <cuda_runtime.h>

#define TT 12
#define SS 16
#define NTHREADS 256
#define YS 17   // y row stride: 16 species + sentinel; odd -> conflict-free gathers
#define FS 13   // rate row stride: 12 rates + pad; odd -> conflict-free reads

struct Params {
    unsigned long long eff2[TT][8]; // effects row as 8 packed f32x2
    int4  idx[TT];                  // x=sub, y=prod, z=fr, w=to (16 = sentinel)
    float rev[TT];                  // 1.0 if reversible else 0.0
    float pad[4];
};

__device__   Params g_p;   // written by prep kernel
__constant__ Params c_p;   // D2D-copied from g_p; read by mech kernel

// Robustly decode one element of a boolean array whose on-device dtype may be
// int32, uint8/bool, or float32. Detection reads only the first 12 bytes.
__device__ __forceinline__ int decode_bool_elem(const unsigned char* p, int i) {
    bool is_f32 = false;                       // float32 1.0f = [00 00 80 3F]
    #pragma unroll
    for (int k = 0; k < 3; k++)
        if (p[4 * k + 2] == 0x80 && p[4 * k + 3] == 0x3F) is_f32 = true;
    if (is_f32) return (((const float*)p)[i] != 0.0f) ? 1 : 0;
    bool off_nonzero = false;                  // uint8: nonzero at off-word bytes
    #pragma unroll
    for (int j = 0; j < 12; j++)
        if ((j & 3) && p[j]) off_nonzero = true;
    if (off_nonzero) return (p[i] != 0) ? 1 : 0;
    return (((const int*)p)[i] != 0) ? 1 : 0;  // int32
}

__global__ void prep_kernel(const float* __restrict__ stoich,
                            const float* __restrict__ effects,
                            const int* __restrict__ from_idx,
                            const unsigned char* __restrict__ from_valid,
                            const int* __restrict__ to_idx,
                            const unsigned char* __restrict__ to_valid,
                            const unsigned char* __restrict__ reversible)
{
    const int t = threadIdx.x;
    if (t >= TT) return;

    float st[SS];
    #pragma unroll
    for (int s = 0; s < SS; s++) st[s] = stoich[t * SS + s];
    int sub = -1, prod = -1;
    #pragma unroll
    for (int s = 0; s < SS; s++) {
        if (st[s] < -0.5f) sub = s;
        if (st[s] >  0.5f) prod = s;
    }
    int4 idx;
    idx.x = (sub  >= 0) ? sub  : 16;
    idx.y = (prod >= 0) ? prod : 16;
    idx.z = decode_bool_elem(from_valid, t) ? from_idx[t] : 16;
    idx.w = decode_bool_elem(to_valid,  t)  ? to_idx[t]   : 16;
    g_p.idx[t] = idx;
    g_p.rev[t] = decode_bool_elem(reversible, t) ? 1.0f : 0.0f;

    #pragma unroll
    for (int j = 0; j < 8; j++) {
        float lo = effects[t * SS + 2 * j];
        float hi = effects[t * SS + 2 * j + 1];
        unsigned long long pk;
        asm("mov.b64 %0, {%1, %2};" : "=l"(pk) : "f"(lo), "f"(hi));
        g_p.eff2[t][j] = pk;
    }
}

__global__ void __launch_bounds__(NTHREADS)
mech_kernel(const float4* __restrict__ y4,
            const float4* __restrict__ f4,
            const float4* __restrict__ r4,
            float4* __restrict__ out4,
            int B)
{
    __shared__ float ys[NTHREADS * YS];
    __shared__ float fs[NTHREADS * FS];
    __shared__ float rs[NTHREADS * FS];

    const int tid  = threadIdx.x;
    const int row0 = blockIdx.x * NTHREADS;
    const int nrow = min(NTHREADS, B - row0);

    // ---- coalesced staging ----
    #pragma unroll
    for (int k = 0; k < 4; k++) {               // y: nrow*4 float4s
        int idx = tid + k * NTHREADS;
        if (idx < nrow * 4) {
            float4 v = y4[(long)row0 * 4 + idx];
            int r = idx >> 2, p = (idx & 3) * 4;
            ys[r * YS + p + 0] = v.x; ys[r * YS + p + 1] = v.y;
            ys[r * YS + p + 2] = v.z; ys[r * YS + p + 3] = v.w;
        }
    }
    ys[tid * YS + 16] = 1.0f;                   // sentinel (own region)

    #pragma unroll
    for (int k = 0; k < 3; k++) {               // f and r: nrow*3 float4s each
        int idx = tid + k * NTHREADS;
        if (idx < nrow * 3) {
            int r = idx / 3, p = (idx - r * 3) * 4;
            float4 a = f4[(long)row0 * 3 + idx];
            fs[r * FS + p + 0] = a.x; fs[r * FS + p + 1] = a.y;
            fs[r * FS + p + 2] = a.z; fs[r * FS + p + 3] = a.w;
            float4 c = r4[(long)row0 * 3 + idx];
            rs[r * FS + p + 0] = c.x; rs[r * FS + p + 1] = c.y;
            rs[r * FS + p + 2] = c.z; rs[r * FS + p + 3] = c.w;
        }
    }
    __syncthreads();

    if (tid < nrow) {
        const int yb = tid * YS;
        const int fb = tid * FS;

        unsigned long long acc2[8];
        #pragma unroll
        for (int j = 0; j < 8; j++) acc2[j] = 0ull;

        #pragma unroll
        for (int t = 0; t < TT; t++) {
            const int4 ci = c_p.idx[t];          // uniform: constant port
            float sc = ys[yb + ci.x];
            float pc = ys[yb + ci.y];
            float ef = ys[yb + ci.z];
            float er = ys[yb + ci.w];
            float v  = fs[fb + t] * ef * sc - c_p.rev[t] * rs[fb + t] * er * pc;
            unsigned long long v2;
            asm("mov.b64 %0, {%1, %1};" : "=l"(v2) : "f"(v));
            #pragma unroll
            for (int j = 0; j < 8; j++)
                asm("fma.rn.f32x2 %0, %1, %2, %3;"
                    : "=l"(acc2[j]) : "l"(v2), "l"(c_p.eff2[t][j]), "l"(acc2[j]));
        }

        // park result in own ys row (gathers for this thread are done)
        #pragma unroll
        for (int j = 0; j < 8; j++) {
            float lo, hi;
            asm("mov.b64 {%0, %1}, %2;" : "=f"(lo), "=f"(hi) : "l"(acc2[j]));
            ys[yb + 2 * j]     = lo;
            ys[yb + 2 * j + 1] = hi;
        }
    }
    __syncthreads();

    // ---- coalesced store ----
    #pragma unroll
    for (int k = 0; k < 4; k++) {
        int idx = tid + k * NTHREADS;
        if (idx < nrow * 4) {
            int r = idx >> 2, p = (idx & 3) * 4;
            float4 o;
            o.x = ys[r * YS + p + 0]; o.y = ys[r * YS + p + 1];
            o.z = ys[r * YS + p + 2]; o.w = ys[r * YS + p + 3];
            out4[(long)row0 * 4 + idx] = o;
        }
    }
}

extern "C" void kernel_launch(void* const* d_in, const int* in_sizes, int n_in,
                              void* d_out, int out_size)
{
    // Input order: t, y, forward_rates, reverse_rates, stoich, effects,
    // from_idx, from_valid, to_idx, to_valid, reversible
    const float* y       = (const float*)d_in[1];
    const float* fr      = (const float*)d_in[2];
    const float* rr      = (const float*)d_in[3];
    const float* stoich  = (const float*)d_in[4];
    const float* effects = (const float*)d_in[5];
    const int*   from_i  = (const int*)d_in[6];
    const unsigned char* from_v = (const unsigned char*)d_in[7];
    const int*   to_i    = (const int*)d_in[8];
    const unsigned char* to_v   = (const unsigned char*)d_in[9];
    const unsigned char* rev    = (const unsigned char*)d_in[10];

    prep_kernel<<<1, 32>>>(stoich, effects, from_i, from_v, to_i, to_v, rev);

    // D2D copy of decoded params into the constant bank (graph-capturable)
    void* g_p_addr = nullptr;
    cudaGetSymbolAddress(&g_p_addr, g_p);
    cudaMemcpyToSymbolAsync(c_p, g_p_addr, sizeof(Params), 0,
                            cudaMemcpyDeviceToDevice, 0);

    const int B = in_sizes[1] / SS;
    const int grid = (B + NTHREADS - 1) / NTHREADS;
    mech_kernel<<<grid, NTHREADS>>>((const float4*)y, (const float4*)fr,
                                    (const float4*)rr, (float4*)d_out, B);
}